// round 9
// baseline (speedup 1.0000x reference)
#include <cuda_runtime.h>
#include <cstdint>

#define BB     16
#define TT     2048
#define HH     512
#define CHUNKS 64
#define LL     (TT / CHUNKS)          // 32
#define NTOT   (BB * TT * HH)         // 16777216
#define HQ     (HH / 4)               // 128 h-quads

#define K_SLOPE  10.0f
#define MAX_PROB 0.8f
#define LOG2E_K  14.4269504088896f    // K_SLOPE * log2(e)

// scratch: per-chunk values E[b][c][h] as float4 quads; after K2 holds
// inclusive end-of-chunk carries. float4 type guarantees 16B alignment.
__device__ float4 g_E4[BB * CHUNKS * HQ];

__device__ __forceinline__ float clamp01(float v) {
    return fminf(fmaxf(v, 0.0f), 1.0f);
}

__device__ __forceinline__ float pow_bL(float b) {
    // b^LL, LL = 32 = 2^5
    float bL = b;
#pragma unroll
    for (int s = 0; s < 5; s++) bL *= bL;
    return bL;
}

__device__ __forceinline__ float ex2_approx(float x) {
    float r;
    asm("ex2.approx.ftz.f32 %0, %1;" : "=f"(r) : "f"(x));
    return r;
}

__device__ __forceinline__ void tf_mix(uint32_t& x0, uint32_t& x1, int r) {
    x0 += x1;
    x1 = __funnelshift_l(x1, x1, r);   // rotl32
    x1 ^= x0;
}

// JAX threefry2x32 (20 rounds), returns o0 ^ o1 (partitionable 32-bit path)
__device__ __forceinline__ uint32_t threefry_xor(uint32_t ks0, uint32_t ks1, uint32_t ks2,
                                                 uint32_t c0, uint32_t c1) {
    uint32_t x0 = c0 + ks0, x1 = c1 + ks1;
    tf_mix(x0, x1, 13); tf_mix(x0, x1, 15); tf_mix(x0, x1, 26); tf_mix(x0, x1, 6);
    x0 += ks1; x1 += ks2 + 1u;
    tf_mix(x0, x1, 17); tf_mix(x0, x1, 29); tf_mix(x0, x1, 16); tf_mix(x0, x1, 24);
    x0 += ks2; x1 += ks0 + 2u;
    tf_mix(x0, x1, 13); tf_mix(x0, x1, 15); tf_mix(x0, x1, 26); tf_mix(x0, x1, 6);
    x0 += ks0; x1 += ks1 + 3u;
    tf_mix(x0, x1, 17); tf_mix(x0, x1, 29); tf_mix(x0, x1, 16); tf_mix(x0, x1, 24);
    x0 += ks1; x1 += ks2 + 4u;
    tf_mix(x0, x1, 13); tf_mix(x0, x1, 15); tf_mix(x0, x1, 26); tf_mix(x0, x1, 6);
    x0 += ks2; x1 += ks0 + 5u;
    return x0 ^ x1;
}

__device__ __forceinline__ float bits_to_uniform(uint32_t bits) {
    return __uint_as_float((bits >> 9) | 0x3f800000u) - 1.0f;
}

// ---------------------------------------------------------------------------
// K1: per-chunk end values, zero initial condition, float4 lanes.
// thread idx -> (b, c, hq), hq fastest (coalesced 16B).
// ---------------------------------------------------------------------------
__global__ void __launch_bounds__(256)
k_chunk_end(const float* __restrict__ x, const float* __restrict__ beta_p) {
    int idx = blockIdx.x * blockDim.x + threadIdx.x;   // 0 .. B*CHUNKS*HQ-1
    float b  = clamp01(beta_p[0]);
    float om = 1.0f - b;

    int hq = idx & (HQ - 1);
    int bc = idx >> 7;            // / HQ
    int c  = bc & (CHUNKS - 1);
    int bi = bc >> 6;             // / CHUNKS

    const float4* xp = (const float4*)x + ((size_t)(bi * TT + c * LL) * HQ + hq);
    float a0 = 0.0f, a1 = 0.0f, a2 = 0.0f, a3 = 0.0f;
#pragma unroll 8
    for (int i = 0; i < LL; i++) {
        float4 xv = xp[(size_t)i * HQ];
        a0 = fmaf(b, a0, om * xv.x);
        a1 = fmaf(b, a1, om * xv.y);
        a2 = fmaf(b, a2, om * xv.z);
        a3 = fmaf(b, a3, om * xv.w);
    }
    float4 e; e.x = a0; e.y = a1; e.z = a2; e.w = a3;
    g_E4[idx] = e;
}

// ---------------------------------------------------------------------------
// K2: in-place prefix over chunks: P[c] = b^L * P[c-1] + E[c], per (b, hq).
// B*HQ = 2048 threads. Tiny.
// ---------------------------------------------------------------------------
__global__ void __launch_bounds__(256)
k_prefix(const float* __restrict__ beta_p) {
    int idx = blockIdx.x * blockDim.x + threadIdx.x;   // 0 .. B*HQ-1
    float b  = clamp01(beta_p[0]);
    float bL = pow_bL(b);

    int hq = idx & (HQ - 1);
    int bi = idx >> 7;

    float p0 = 0.0f, p1 = 0.0f, p2 = 0.0f, p3 = 0.0f;
#pragma unroll 4
    for (int c = 0; c < CHUNKS; c++) {
        size_t off = (size_t)(bi * CHUNKS + c) * HQ + hq;
        float4 e = g_E4[off];
        p0 = fmaf(bL, p0, e.x);
        p1 = fmaf(bL, p1, e.y);
        p2 = fmaf(bL, p2, e.z);
        p3 = fmaf(bL, p3, e.w);
        e.x = p0; e.y = p1; e.z = p2; e.w = p3;
        g_E4[off] = e;
    }
}

// ---------------------------------------------------------------------------
// K3: main pass, float4 lanes -> 4 independent threefry chains per thread
// (fills dep-chain stall slots). carry = P[b][c-1], re-scan chunk, fused
// sigmoid + partitionable-threefry bernoulli.
// ---------------------------------------------------------------------------
__global__ void __launch_bounds__(128)
k_main(const float* __restrict__ x,
       const float* __restrict__ beta_p,
       const int*   __restrict__ seed_p,
       float* __restrict__ out) {
    int idx = blockIdx.x * blockDim.x + threadIdx.x;   // 0 .. B*CHUNKS*HQ-1
    float b  = clamp01(beta_p[0]);
    float om = 1.0f - b;

    int hq = idx & (HQ - 1);
    int bc = idx >> 7;
    int c  = bc & (CHUNKS - 1);
    int bi = bc >> 6;

    int h = hq * 4;

    // carry-in = inclusive carry of chunk c-1 (L2-hot, 2MB)
    float v0 = 0.0f, v1 = 0.0f, v2 = 0.0f, v3 = 0.0f;
    if (c > 0) {
        float4 e = g_E4[(size_t)(bi * CHUNKS + c - 1) * HQ + hq];
        v0 = e.x; v1 = e.y; v2 = e.z; v3 = e.w;
    }

    // threefry key schedule: key = (0, seed)
    uint32_t ks0 = 0u;
    uint32_t ks1 = (uint32_t)seed_p[0];
    uint32_t ks2 = ks0 ^ ks1 ^ 0x1BD11BDAu;

    uint32_t base = (uint32_t)((bi * TT + c * LL) * HH + h);  // flat elem idx
    const float4* xp = (const float4*)(x + base);
    float4* spikes = (float4*)(out + base);
    float4* vout   = (float4*)(out + NTOT + base);

#pragma unroll 2
    for (int i = 0; i < LL; i++) {
        float4 xv = xp[(size_t)i * HQ];
        v0 = fmaf(b, v0, om * xv.x);
        v1 = fmaf(b, v1, om * xv.y);
        v2 = fmaf(b, v2, om * xv.z);
        v3 = fmaf(b, v3, om * xv.w);

        // p = MAX_PROB / (1 + exp(-K*(V-1))) ; exp via single FMA + EX2
        float e0 = ex2_approx(fmaf(-LOG2E_K, v0, LOG2E_K));
        float e1 = ex2_approx(fmaf(-LOG2E_K, v1, LOG2E_K));
        float e2 = ex2_approx(fmaf(-LOG2E_K, v2, LOG2E_K));
        float e3 = ex2_approx(fmaf(-LOG2E_K, v3, LOG2E_K));
        float p0 = __fdividef(MAX_PROB, 1.0f + e0);
        float p1 = __fdividef(MAX_PROB, 1.0f + e1);
        float p2 = __fdividef(MAX_PROB, 1.0f + e2);
        float p3 = __fdividef(MAX_PROB, 1.0f + e3);

        uint32_t j0 = base + (uint32_t)i * HH;    // element flat index (hi word = 0)
        uint32_t r0 = threefry_xor(ks0, ks1, ks2, 0u, j0);
        uint32_t r1 = threefry_xor(ks0, ks1, ks2, 0u, j0 + 1u);
        uint32_t r2 = threefry_xor(ks0, ks1, ks2, 0u, j0 + 2u);
        uint32_t r3 = threefry_xor(ks0, ks1, ks2, 0u, j0 + 3u);

        float4 s, vv;
        s.x = (bits_to_uniform(r0) < p0) ? 1.0f : 0.0f;
        s.y = (bits_to_uniform(r1) < p1) ? 1.0f : 0.0f;
        s.z = (bits_to_uniform(r2) < p2) ? 1.0f : 0.0f;
        s.w = (bits_to_uniform(r3) < p3) ? 1.0f : 0.0f;
        vv.x = v0; vv.y = v1; vv.z = v2; vv.w = v3;
        spikes[(size_t)i * HQ] = s;
        vout[(size_t)i * HQ]   = vv;
    }
}

extern "C" void kernel_launch(void* const* d_in, const int* in_sizes, int n_in,
                              void* d_out, int out_size) {
    const float* x    = (const float*)d_in[0];
    const float* beta = (const float*)d_in[1];
    const int*   seed = (const int*)d_in[2];
    float*       out  = (float*)d_out;

    (void)in_sizes; (void)n_in; (void)out_size;

    // K1: B*CHUNKS*HQ = 131072 threads (float4 lanes)
    k_chunk_end<<<(BB * CHUNKS * HQ) / 256, 256>>>(x, beta);
    // K2: B*HQ = 2048 threads, prefix over 64 chunks
    k_prefix<<<(BB * HQ) / 256, 256>>>(beta);
    // K3: B*CHUNKS*HQ = 131072 threads, 4 RNG chains each
    k_main<<<(BB * CHUNKS * HQ) / 128, 128>>>(x, beta, seed, out);
}

// round 11
// speedup vs baseline: 1.1079x; 1.1079x over previous
#include <cuda_runtime.h>
#include <cstdint>

#define BB     16
#define TT     2048
#define HH     512
#define CHUNKS 64
#define LL     (TT / CHUNKS)          // 32
#define NTOT   (BB * TT * HH)         // 16777216
#define HP     (HH / 2)               // 256 h-pairs

#define MAX_PROB 0.8f
#define LOG2E_K  14.4269504088896f    // K_SLOPE * log2(e)

// scratch: per-chunk values E[b][c][h]; after K2 holds inclusive carries
__device__ float2 g_E2[BB * CHUNKS * HP];

__device__ __forceinline__ float clamp01(float v) {
    return fminf(fmaxf(v, 0.0f), 1.0f);
}

__device__ __forceinline__ float pow_bL(float b) {
    // b^LL, LL = 32 = 2^5
    float bL = b;
#pragma unroll
    for (int s = 0; s < 5; s++) bL *= bL;
    return bL;
}

__device__ __forceinline__ float ex2_approx(float x) {
    float r;
    asm("ex2.approx.ftz.f32 %0, %1;" : "=f"(r) : "f"(x));
    return r;
}

__device__ __forceinline__ void tf_mix(uint32_t& x0, uint32_t& x1, int r) {
    x0 += x1;
    x1 = __funnelshift_l(x1, x1, r);   // rotl32
    x1 ^= x0;
}

// JAX threefry2x32 (20 rounds), returns o0 ^ o1 (partitionable 32-bit path)
__device__ __forceinline__ uint32_t threefry_xor(uint32_t ks0, uint32_t ks1, uint32_t ks2,
                                                 uint32_t c0, uint32_t c1) {
    uint32_t x0 = c0 + ks0, x1 = c1 + ks1;
    tf_mix(x0, x1, 13); tf_mix(x0, x1, 15); tf_mix(x0, x1, 26); tf_mix(x0, x1, 6);
    x0 += ks1; x1 += ks2 + 1u;
    tf_mix(x0, x1, 17); tf_mix(x0, x1, 29); tf_mix(x0, x1, 16); tf_mix(x0, x1, 24);
    x0 += ks2; x1 += ks0 + 2u;
    tf_mix(x0, x1, 13); tf_mix(x0, x1, 15); tf_mix(x0, x1, 26); tf_mix(x0, x1, 6);
    x0 += ks0; x1 += ks1 + 3u;
    tf_mix(x0, x1, 17); tf_mix(x0, x1, 29); tf_mix(x0, x1, 16); tf_mix(x0, x1, 24);
    x0 += ks1; x1 += ks2 + 4u;
    tf_mix(x0, x1, 13); tf_mix(x0, x1, 15); tf_mix(x0, x1, 26); tf_mix(x0, x1, 6);
    x0 += ks2; x1 += ks0 + 5u;
    return x0 ^ x1;
}

__device__ __forceinline__ float bits_to_uniform(uint32_t bits) {
    return __uint_as_float((bits >> 9) | 0x3f800000u) - 1.0f;
}

// ---------------------------------------------------------------------------
// K1: per-chunk end values, zero IC, float2 lanes (R7-measured: 14.0us).
// ---------------------------------------------------------------------------
__global__ void __launch_bounds__(256)
k_chunk_end(const float* __restrict__ x, const float* __restrict__ beta_p) {
    int idx = blockIdx.x * blockDim.x + threadIdx.x;   // 0 .. B*CHUNKS*HP-1
    float b  = clamp01(beta_p[0]);
    float om = 1.0f - b;

    int hp = idx & (HP - 1);
    int bc = idx >> 8;            // / HP
    int c  = bc & (CHUNKS - 1);
    int bi = bc >> 6;             // / CHUNKS

    const float2* xp = (const float2*)x + ((size_t)(bi * TT + c * LL) * HP + hp);
    float a0 = 0.0f, a1 = 0.0f;
#pragma unroll 8
    for (int i = 0; i < LL; i++) {
        float2 xv = xp[(size_t)i * HP];
        a0 = fmaf(b, a0, om * xv.x);
        a1 = fmaf(b, a1, om * xv.y);
    }
    float2 e; e.x = a0; e.y = a1;
    g_E2[idx] = e;
}

// ---------------------------------------------------------------------------
// K2: in-place prefix over chunks: P[c] = b^L * P[c-1] + E[c], per (b, hp).
// ---------------------------------------------------------------------------
__global__ void __launch_bounds__(256)
k_prefix(const float* __restrict__ beta_p) {
    int idx = blockIdx.x * blockDim.x + threadIdx.x;   // 0 .. B*HP-1
    float b  = clamp01(beta_p[0]);
    float bL = pow_bL(b);

    int hp = idx & (HP - 1);
    int bi = idx >> 8;

    float p0 = 0.0f, p1 = 0.0f;
#pragma unroll 4
    for (int c = 0; c < CHUNKS; c++) {
        size_t off = (size_t)(bi * CHUNKS + c) * HP + hp;
        float2 e = g_E2[off];
        p0 = fmaf(bL, p0, e.x);
        p1 = fmaf(bL, p1, e.y);
        e.x = p0; e.y = p1;
        g_E2[off] = e;
    }
}

// ---------------------------------------------------------------------------
// K3: main pass, float2 lanes. __launch_bounds__(256, 4) gives ptxas a 64-reg
// budget so the unrolled threefry chains actually interleave in SASS instead
// of being serialized to fit 32 regs (the R4/R7/R9 issue ceiling).
// Spike test: u < 0.8/(1+e)  <=>  fmaf(u,e,u) < 0.8  (saves FADD+RCP+FMUL).
// ---------------------------------------------------------------------------
__global__ void __launch_bounds__(256, 4)
k_main(const float* __restrict__ x,
       const float* __restrict__ beta_p,
       const int*   __restrict__ seed_p,
       float* __restrict__ out) {
    int idx = blockIdx.x * blockDim.x + threadIdx.x;   // 0 .. B*CHUNKS*HP-1
    float b  = clamp01(beta_p[0]);
    float om = 1.0f - b;

    int hp = idx & (HP - 1);
    int bc = idx >> 8;
    int c  = bc & (CHUNKS - 1);
    int bi = bc >> 6;

    int h = hp * 2;

    // carry-in = inclusive carry of chunk c-1 (L2-hot, 2MB)
    float v0 = 0.0f, v1 = 0.0f;
    if (c > 0) {
        float2 e = g_E2[(size_t)(bi * CHUNKS + c - 1) * HP + hp];
        v0 = e.x; v1 = e.y;
    }

    // threefry key schedule: key = (0, seed)
    uint32_t ks0 = 0u;
    uint32_t ks1 = (uint32_t)seed_p[0];
    uint32_t ks2 = ks0 ^ ks1 ^ 0x1BD11BDAu;

    uint32_t base = (uint32_t)((bi * TT + c * LL) * HH + h);  // flat elem idx
    const float2* xp = (const float2*)(x + base);
    float2* spikes = (float2*)(out + base);
    float2* vout   = (float2*)(out + NTOT + base);

#pragma unroll 4
    for (int i = 0; i < LL; i++) {
        float2 xv = xp[(size_t)i * HP];
        v0 = fmaf(b, v0, om * xv.x);
        v1 = fmaf(b, v1, om * xv.y);

        // e = exp(-K*(V-1)) via single FMA + EX2 (R9-verified rounding)
        float e0 = ex2_approx(fmaf(-LOG2E_K, v0, LOG2E_K));
        float e1 = ex2_approx(fmaf(-LOG2E_K, v1, LOG2E_K));

        uint32_t j0 = base + (uint32_t)i * HH;    // element flat index (hi word = 0)
        uint32_t r0 = threefry_xor(ks0, ks1, ks2, 0u, j0);
        uint32_t r1 = threefry_xor(ks0, ks1, ks2, 0u, j0 + 1u);
        float u0 = bits_to_uniform(r0);
        float u1 = bits_to_uniform(r1);

        // u < 0.8/(1+e)  <=>  u*(1+e) < 0.8
        float2 s, vv;
        s.x = (fmaf(u0, e0, u0) < MAX_PROB) ? 1.0f : 0.0f;
        s.y = (fmaf(u1, e1, u1) < MAX_PROB) ? 1.0f : 0.0f;
        vv.x = v0; vv.y = v1;
        spikes[(size_t)i * HP] = s;
        vout[(size_t)i * HP]   = vv;
    }
}

extern "C" void kernel_launch(void* const* d_in, const int* in_sizes, int n_in,
                              void* d_out, int out_size) {
    const float* x    = (const float*)d_in[0];
    const float* beta = (const float*)d_in[1];
    const int*   seed = (const int*)d_in[2];
    float*       out  = (float*)d_out;

    (void)in_sizes; (void)n_in; (void)out_size;

    // K1: B*CHUNKS*HP = 262144 threads (float2 lanes)
    k_chunk_end<<<(BB * CHUNKS * HP) / 256, 256>>>(x, beta);
    // K2: B*HP = 4096 threads, prefix over 64 chunks
    k_prefix<<<(BB * HP) / 256, 256>>>(beta);
    // K3: B*CHUNKS*HP = 262144 threads, 64-reg budget for chain interleave
    k_main<<<(BB * CHUNKS * HP) / 256, 256>>>(x, beta, seed, out);
}